// round 2
// baseline (speedup 1.0000x reference)
#include <cuda_runtime.h>
#include <math.h>

#define NS     131072
#define LE     100
#define LD     50
#define HD     200
#define SPD    202
#define BT     64          // samples per CTA
#define THREADS 256
#define PITCH  204         // h/sig row pitch (floats): 816B, 16B aligned, conflict-free LDS.128

typedef unsigned long long ull;

__device__ __forceinline__ ull fma2(ull a, ull b, ull c) {
    ull d;
    asm("fma.rn.f32x2 %0, %1, %2, %3;" : "=l"(d) : "l"(a), "l"(b), "l"(c));
    return d;
}
__device__ __forceinline__ float red2(ull v) {
    float lo, hi;
    asm("mov.b64 {%0, %1}, %2;" : "=f"(lo), "=f"(hi) : "l"(v));
    return lo + hi;
}

// dot product over N2 float2-pairs (8B-aligned), packed f32x2 FMAs
template <int N2>
__device__ __forceinline__ float dot64(const float* __restrict__ a, const float* __restrict__ b) {
    const ull* A = (const ull*)a;
    const ull* B = (const ull*)b;
    ull a0 = 0ull, a1 = 0ull;
    int i = 0;
#pragma unroll 8
    for (; i + 2 <= N2; i += 2) {
        a0 = fma2(A[i], B[i], a0);
        a1 = fma2(A[i + 1], B[i + 1], a1);
    }
    if (i < N2) a0 = fma2(A[i], B[i], a0);
    return red2(a0) + red2(a1);
}

__device__ __forceinline__ float lrelu(float x) { return x > 0.f ? x : 0.01f * x; }
__device__ __forceinline__ float sigm(float x) { return 1.0f / (1.0f + expf(-x)); }

// smem layout (floats)
#define OFF_SIG  0                       // 64*204  (sig, reused as x2)
#define OFF_H0   (BT * PITCH)            // 64*204  h ping
#define OFF_H1   (2 * BT * PITCH)        // 64*204  h pong
#define OFF_XB   (3 * BT * PITCH)        // 64*100  (x1 / y1)
#define OFF_Y2   (OFF_XB + BT * 100)     // 64*52
#define OFF_DIN  (OFF_Y2 + BT * 52)      // 64
#define OFF_CT   (OFF_DIN + BT)          // 100
#define OFF_ST   (OFF_CT + 100)          // 100
#define SMEM_FLOATS (OFF_ST + 100)
#define SMEM_BYTES  (SMEM_FLOATS * 4)

__global__ void __launch_bounds__(THREADS, 1)
seq2seq_gru_kernel(
    const float* __restrict__ enc_in,
    const float* __restrict__ enc_w1, const float* __restrict__ enc_b1,
    const float* __restrict__ enc_w2, const float* __restrict__ enc_b2,
    const float* __restrict__ enc_wl, const float* __restrict__ enc_bl,
    const float* __restrict__ w_ih,  const float* __restrict__ w_hh,
    const float* __restrict__ b_ih,  const float* __restrict__ b_hh,
    const float* __restrict__ dec_w1, const float* __restrict__ dec_b1,
    const float* __restrict__ dec_w2, const float* __restrict__ dec_b2,
    const float* __restrict__ dec_w3, const float* __restrict__ dec_b3,
    float* __restrict__ out)
{
    extern __shared__ float sm[];
    float* sig  = sm + OFF_SIG;
    float* hb0  = sm + OFF_H0;
    float* hb1  = sm + OFF_H1;
    float* xbuf = sm + OFF_XB;
    float* y2b  = sm + OFF_Y2;
    float* din  = sm + OFF_DIN;
    float* ctab = sm + OFF_CT;
    float* stab = sm + OFF_ST;

    const int tid  = threadIdx.x;
    const int lane = tid & 31;
    const int w    = tid >> 5;             // 8 warps
    const int cta  = blockIdx.x;
    const float* inbase = enc_in + (size_t)cta * BT * LE;

    // ---- stage raw signal into sig[s][0..99], coalesced ----
    for (int idx = tid; idx < BT * LE; idx += THREADS) {
        int s = idx / LE, t = idx - s * LE;
        sig[s * PITCH + t] = inbase[idx];
    }
    // twiddle tables: exact zeros at multiples of pi via sinpif/cospif
    if (tid < 100) {
        float u = (float)tid / 50.0f;      // 2*m/100
        ctab[tid] = cospif(u);
        stab[tid] = sinpif(u);
    }
    if (tid < BT) din[tid] = inbase[tid * LE + (LE - 1)];
    __syncthreads();

    // ---- DFT features: sig[s][100+k]=|f|, sig[s][151+k]=angle ----
    for (int kk = 0; kk < 7; ++kk) {
        int k = w + 8 * kk;
        if (k < 51) {
#pragma unroll
            for (int p = 0; p < 2; ++p) {
                int s = lane + 32 * p;
                const float* xr = sig + s * PITCH;
                float re = 0.f, im = 0.f;
                int m = 0;
                for (int t = 0; t < LE; ++t) {
                    float xv = xr[t];
                    re += xv * ctab[m];
                    im -= xv * stab[m];
                    m += k; if (m >= 100) m -= 100;
                }
                re *= 0.01f; im *= 0.01f;      // norm='forward'
                if (k == 0 || k == 50) im = 0.0f;  // exact-zero imag bins (match pocketfft)
                sig[s * PITCH + 100 + k] = sqrtf(re * re + im * im);
                sig[s * PITCH + 151 + k] = atan2f(im, re);
            }
        }
    }
    __syncthreads();

    // ---- encoder layer 1: [202]->[100], lrelu ----
    for (int ii = 0; ii < 13; ++ii) {
        int i = w + 8 * ii;
        if (i < 100) {
            float b = enc_b1[i];
            const float* wr = enc_w1 + (size_t)i * SPD;
#pragma unroll
            for (int p = 0; p < 2; ++p) {
                int s = lane + 32 * p;
                xbuf[s * 100 + i] = lrelu(dot64<101>(sig + s * PITCH, wr) + b);
            }
        }
    }
    __syncthreads();
    // ---- encoder layer 2: [100]->[202], lrelu (writes back into sig) ----
    for (int ii = 0; ii < 26; ++ii) {
        int i = w + 8 * ii;
        if (i < SPD) {
            float b = enc_b2[i];
            const float* wr = enc_w2 + (size_t)i * 100;
#pragma unroll
            for (int p = 0; p < 2; ++p) {
                int s = lane + 32 * p;
                sig[s * PITCH + i] = lrelu(dot64<50>(xbuf + s * 100, wr) + b);
            }
        }
    }
    __syncthreads();

    // ---- encoder final: [202]->[200] -> h0 ----
    for (int ii = 0; ii < 25; ++ii) {
        int i = w + 8 * ii;
        float b = enc_bl[i];
        const float* wr = enc_wl + (size_t)i * SPD;
#pragma unroll
        for (int p = 0; p < 2; ++p) {
            int s = lane + 32 * p;
            hb0[s * PITCH + i] = dot64<101>(sig + s * PITCH, wr) + b;
        }
    }
    __syncthreads();

    // ---- decoder loop ----
    for (int t = 0; t < LD; ++t) {
        float* hc = (t & 1) ? hb1 : hb0;
        float* hn = (t & 1) ? hb0 : hb1;

        const float dA = din[lane];
        const float dB = din[lane + 32];

        // GRU: each lane owns sample pair (lane, lane+32); warp owns j = w+8*jj
        const ulonglong2* hA = (const ulonglong2*)(hc + lane * PITCH);
        const ulonglong2* hB = (const ulonglong2*)(hc + (lane + 32) * PITCH);

        for (int jj = 0; jj < 25; ++jj) {
            int j = w + 8 * jj;
            const ulonglong2* wr = (const ulonglong2*)(w_hh + (size_t)j * HD);
            const ulonglong2* wz = wr + (size_t)HD * HD / 4;   // +200 rows
            const ulonglong2* wn = wr + (size_t)2 * HD * HD / 4;

            ull aRA = 0, aZA = 0, aNA = 0, aRB = 0, aZB = 0, aNB = 0;
#pragma unroll 5
            for (int i = 0; i < HD / 4; ++i) {        // 50 x 16B chunks = 200 floats
                ulonglong2 ha = hA[i], hb = hB[i];
                ulonglong2 r = wr[i], z = wz[i], n = wn[i];
                aRA = fma2(ha.x, r.x, aRA);  aRB = fma2(hb.x, r.x, aRB);
                aZA = fma2(ha.x, z.x, aZA);  aZB = fma2(hb.x, z.x, aZB);
                aNA = fma2(ha.x, n.x, aNA);  aNB = fma2(hb.x, n.x, aNB);
                aRA = fma2(ha.y, r.y, aRA);  aRB = fma2(hb.y, r.y, aRB);
                aZA = fma2(ha.y, z.y, aZA);  aZB = fma2(hb.y, z.y, aZB);
                aNA = fma2(ha.y, n.y, aNA);  aNB = fma2(hb.y, n.y, aNB);
            }
            float bhr = b_hh[j], bhz = b_hh[HD + j], bhn = b_hh[2 * HD + j];
            float xr0 = b_ih[j], xz0 = b_ih[HD + j], xn0 = b_ih[2 * HD + j];
            float wir = w_ih[j], wiz = w_ih[HD + j], win = w_ih[2 * HD + j];

            {   // sample A
                float hr = red2(aRA) + bhr, hz = red2(aZA) + bhz, hn_g = red2(aNA) + bhn;
                float r = sigm(fmaf(dA, wir, xr0) + hr);
                float z = sigm(fmaf(dA, wiz, xz0) + hz);
                float n = tanhf(fmaf(dA, win, xn0) + r * hn_g);
                hn[lane * PITCH + j] = (1.f - z) * n + z * hc[lane * PITCH + j];
            }
            {   // sample B
                float hr = red2(aRB) + bhr, hz = red2(aZB) + bhz, hn_g = red2(aNB) + bhn;
                float r = sigm(fmaf(dB, wir, xr0) + hr);
                float z = sigm(fmaf(dB, wiz, xz0) + hz);
                float n = tanhf(fmaf(dB, win, xn0) + r * hn_g);
                hn[(lane + 32) * PITCH + j] = (1.f - z) * n + z * hc[(lane + 32) * PITCH + j];
            }
        }
        __syncthreads();

        // dec layer 1: [200]->[100], lrelu
        for (int ii = 0; ii < 13; ++ii) {
            int i = w + 8 * ii;
            if (i < 100) {
                float b = dec_b1[i];
                const float* wr1 = dec_w1 + (size_t)i * HD;
#pragma unroll
                for (int p = 0; p < 2; ++p) {
                    int s = lane + 32 * p;
                    xbuf[s * 100 + i] = lrelu(dot64<100>(hn + s * PITCH, wr1) + b);
                }
            }
        }
        __syncthreads();
        // dec layer 2: [100]->[50], lrelu
        for (int ii = 0; ii < 7; ++ii) {
            int i = w + 8 * ii;
            if (i < 50) {
                float b = dec_b2[i];
                const float* wr2 = dec_w2 + (size_t)i * 100;
#pragma unroll
                for (int p = 0; p < 2; ++p) {
                    int s = lane + 32 * p;
                    y2b[s * 52 + i] = lrelu(dot64<50>(xbuf + s * 100, wr2) + b);
                }
            }
        }
        __syncthreads();
        // dec layer 3: [50]->[1]; store output, feed back dec_in
        if (w == 0) {
            float b3 = dec_b3[0];
#pragma unroll
            for (int p = 0; p < 2; ++p) {
                int s = lane + 32 * p;
                float v = dot64<25>(y2b + s * 52, dec_w3) + b3;
                out[((size_t)(cta * BT + s)) * LD + t] = v;
                din[s] = v;
            }
        }
        __syncthreads();
    }
}

extern "C" void kernel_launch(void* const* d_in, const int* in_sizes, int n_in,
                              void* d_out, int out_size) {
    const float* enc_in = (const float*)d_in[0];
    const float* enc_w1 = (const float*)d_in[1];
    const float* enc_b1 = (const float*)d_in[2];
    const float* enc_w2 = (const float*)d_in[3];
    const float* enc_b2 = (const float*)d_in[4];
    const float* enc_wl = (const float*)d_in[5];
    const float* enc_bl = (const float*)d_in[6];
    const float* w_ih   = (const float*)d_in[7];
    const float* w_hh   = (const float*)d_in[8];
    const float* b_ih   = (const float*)d_in[9];
    const float* b_hh   = (const float*)d_in[10];
    const float* dec_w1 = (const float*)d_in[11];
    const float* dec_b1 = (const float*)d_in[12];
    const float* dec_w2 = (const float*)d_in[13];
    const float* dec_b2 = (const float*)d_in[14];
    const float* dec_w3 = (const float*)d_in[15];
    const float* dec_b3 = (const float*)d_in[16];
    float* out = (float*)d_out;

    cudaFuncSetAttribute(seq2seq_gru_kernel,
                         cudaFuncAttributeMaxDynamicSharedMemorySize, SMEM_BYTES);
    seq2seq_gru_kernel<<<NS / BT, THREADS, SMEM_BYTES>>>(
        enc_in, enc_w1, enc_b1, enc_w2, enc_b2, enc_wl, enc_bl,
        w_ih, w_hh, b_ih, b_hh,
        dec_w1, dec_b1, dec_w2, dec_b2, dec_w3, dec_b3, out);
}

// round 3
// speedup vs baseline: 1.2947x; 1.2947x over previous
#include <cuda_runtime.h>
#include <math.h>

#define NS     131072
#define LE     100
#define LD     50
#define HD     200
#define SPD    202
#define BT     64          // samples per CTA
#define THREADS 256
#define PITCH  204         // row pitch (floats): 816B = 51*16B, conflict-free LDS.128

typedef unsigned long long ull;

__device__ __forceinline__ ull fma2(ull a, ull b, ull c) {
    ull d;
    asm("fma.rn.f32x2 %0, %1, %2, %3;" : "=l"(d) : "l"(a), "l"(b), "l"(c));
    return d;
}
__device__ __forceinline__ float red2(ull v) {
    float lo, hi;
    asm("mov.b64 {%0, %1}, %2;" : "=f"(lo), "=f"(hi) : "l"(v));
    return lo + hi;
}

// dot over N2 8B-units: A from smem (16B-aligned, LDS.128), B global (8B loads)
template <int N2>
__device__ __forceinline__ float dotAB(const float* __restrict__ a, const float* __restrict__ b) {
    const ulonglong2* A2 = (const ulonglong2*)a;
    const ull* B = (const ull*)b;
    ull a0 = 0ull, a1 = 0ull;
#pragma unroll
    for (int i = 0; i < N2 / 2; ++i) {
        ulonglong2 x = A2[i];
        a0 = fma2(x.x, B[2 * i], a0);
        a1 = fma2(x.y, B[2 * i + 1], a1);
    }
    if (N2 & 1) a0 = fma2(((const ull*)a)[N2 - 1], B[N2 - 1], a0);
    return red2(a0) + red2(a1);
}

__device__ __forceinline__ float lrelu(float x) { return x > 0.f ? x : 0.01f * x; }
// fast, overflow-safe gates (plenty of headroom vs 1e-3 threshold)
__device__ __forceinline__ float sigm(float x) { return 1.0f / (1.0f + __expf(-x)); }
__device__ __forceinline__ float tanh_f(float x) {
    float t = __expf(-2.0f * fabsf(x));          // in (0,1], no overflow
    float r = (1.0f - t) / (1.0f + t);
    return copysignf(r, x);
}

// smem layout (floats)
#define OFF_SIG  0
#define OFF_H0   (BT * PITCH)
#define OFF_H1   (2 * BT * PITCH)
#define OFF_XB   (3 * BT * PITCH)
#define OFF_Y2   (OFF_XB + BT * 100)
#define OFF_DIN  (OFF_Y2 + BT * 52)
#define OFF_CT   (OFF_DIN + BT)
#define OFF_ST   (OFF_CT + 100)
#define SMEM_FLOATS (OFF_ST + 100)
#define SMEM_BYTES  (SMEM_FLOATS * 4)

#define JG 5   // j's per register-blocked pass
#define NP 5   // passes (JG*NP = 25 j per warp)

__global__ void __launch_bounds__(THREADS, 1)
seq2seq_gru_kernel(
    const float* __restrict__ enc_in,
    const float* __restrict__ enc_w1, const float* __restrict__ enc_b1,
    const float* __restrict__ enc_w2, const float* __restrict__ enc_b2,
    const float* __restrict__ enc_wl, const float* __restrict__ enc_bl,
    const float* __restrict__ w_ih,  const float* __restrict__ w_hh,
    const float* __restrict__ b_ih,  const float* __restrict__ b_hh,
    const float* __restrict__ dec_w1, const float* __restrict__ dec_b1,
    const float* __restrict__ dec_w2, const float* __restrict__ dec_b2,
    const float* __restrict__ dec_w3, const float* __restrict__ dec_b3,
    float* __restrict__ out)
{
    extern __shared__ float sm[];
    float* sig  = sm + OFF_SIG;
    float* hb0  = sm + OFF_H0;
    float* hb1  = sm + OFF_H1;
    float* xbuf = sm + OFF_XB;
    float* y2b  = sm + OFF_Y2;
    float* din  = sm + OFF_DIN;
    float* ctab = sm + OFF_CT;
    float* stab = sm + OFF_ST;

    const int tid  = threadIdx.x;
    const int lane = tid & 31;
    const int w    = tid >> 5;             // 8 warps
    const int cta  = blockIdx.x;
    const float* inbase = enc_in + (size_t)cta * BT * LE;

    // ---- stage raw signal ----
    for (int idx = tid; idx < BT * LE; idx += THREADS) {
        int s = idx / LE, t = idx - s * LE;
        sig[s * PITCH + t] = inbase[idx];
    }
    if (tid < 100) {
        float u = (float)tid / 50.0f;
        ctab[tid] = cospif(u);
        stab[tid] = sinpif(u);
    }
    if (tid < BT) din[tid] = inbase[tid * LE + (LE - 1)];
    __syncthreads();

    // ---- DFT features ----
    for (int kk = 0; kk < 7; ++kk) {
        int k = w + 8 * kk;
        if (k < 51) {
#pragma unroll
            for (int p = 0; p < 2; ++p) {
                int s = lane + 32 * p;
                const float* xr = sig + s * PITCH;
                float re = 0.f, im = 0.f;
                int m = 0;
                for (int t = 0; t < LE; ++t) {
                    float xv = xr[t];
                    re += xv * ctab[m];
                    im -= xv * stab[m];
                    m += k; if (m >= 100) m -= 100;
                }
                re *= 0.01f; im *= 0.01f;
                if (k == 0 || k == 50) im = 0.0f;
                sig[s * PITCH + 100 + k] = sqrtf(re * re + im * im);
                sig[s * PITCH + 151 + k] = atan2f(im, re);
            }
        }
    }
    __syncthreads();

    // ---- encoder layer 1: [202]->[100] ----
    for (int ii = 0; ii < 13; ++ii) {
        int i = w + 8 * ii;
        if (i < 100) {
            float b = enc_b1[i];
            const float* wr = enc_w1 + (size_t)i * SPD;
#pragma unroll
            for (int p = 0; p < 2; ++p) {
                int s = lane + 32 * p;
                xbuf[s * 100 + i] = lrelu(dotAB<101>(sig + s * PITCH, wr) + b);
            }
        }
    }
    __syncthreads();
    // ---- encoder layer 2: [100]->[202] ----
    for (int ii = 0; ii < 26; ++ii) {
        int i = w + 8 * ii;
        if (i < SPD) {
            float b = enc_b2[i];
            const float* wr = enc_w2 + (size_t)i * 100;
#pragma unroll
            for (int p = 0; p < 2; ++p) {
                int s = lane + 32 * p;
                sig[s * PITCH + i] = lrelu(dotAB<50>(xbuf + s * 100, wr) + b);
            }
        }
    }
    __syncthreads();
    // ---- encoder final: [202]->[200] -> h0 ----
    for (int ii = 0; ii < 25; ++ii) {
        int i = w + 8 * ii;
        float b = enc_bl[i];
        const float* wr = enc_wl + (size_t)i * SPD;
#pragma unroll
        for (int p = 0; p < 2; ++p) {
            int s = lane + 32 * p;
            hb0[s * PITCH + i] = dotAB<101>(sig + s * PITCH, wr) + b;
        }
    }
    __syncthreads();

    const int jbase = w * 25;   // warp owns 25 consecutive j

    // ---- decoder loop ----
    for (int t = 0; t < LD; ++t) {
        float* hc = (t & 1) ? hb1 : hb0;
        float* hn = (t & 1) ? hb0 : hb1;

        const float dA = din[lane];
        const float dB = din[lane + 32];

        const ulonglong2* hA = (const ulonglong2*)(hc + lane * PITCH);
        const ulonglong2* hB = (const ulonglong2*)(hc + (lane + 32) * PITCH);

        for (int g = 0; g < NP; ++g) {
            const int j0 = jbase + g * JG;
            // weight row base (ulonglong2 units, 50 per row)
            const ulonglong2* Wr = (const ulonglong2*)w_hh + (size_t)j0 * 50;
            const ulonglong2* Wz = Wr + 10000;   // +200 rows
            const ulonglong2* Wn = Wr + 20000;   // +400 rows

            ull aR[JG][2], aZ[JG][2], aN[JG][2];
#pragma unroll
            for (int u = 0; u < JG; ++u) {
                aR[u][0] = aR[u][1] = 0ull;
                aZ[u][0] = aZ[u][1] = 0ull;
                aN[u][0] = aN[u][1] = 0ull;
            }

#pragma unroll 2
            for (int i = 0; i < HD / 4; ++i) {      // 50 chunks of 16B
                ulonglong2 ha = hA[i], hb = hB[i];
#pragma unroll
                for (int u = 0; u < JG; ++u) {
                    ulonglong2 wv = Wr[u * 50 + i];
                    aR[u][0] = fma2(ha.x, wv.x, aR[u][0]);
                    aR[u][0] = fma2(ha.y, wv.y, aR[u][0]);
                    aR[u][1] = fma2(hb.x, wv.x, aR[u][1]);
                    aR[u][1] = fma2(hb.y, wv.y, aR[u][1]);
                }
#pragma unroll
                for (int u = 0; u < JG; ++u) {
                    ulonglong2 wv = Wz[u * 50 + i];
                    aZ[u][0] = fma2(ha.x, wv.x, aZ[u][0]);
                    aZ[u][0] = fma2(ha.y, wv.y, aZ[u][0]);
                    aZ[u][1] = fma2(hb.x, wv.x, aZ[u][1]);
                    aZ[u][1] = fma2(hb.y, wv.y, aZ[u][1]);
                }
#pragma unroll
                for (int u = 0; u < JG; ++u) {
                    ulonglong2 wv = Wn[u * 50 + i];
                    aN[u][0] = fma2(ha.x, wv.x, aN[u][0]);
                    aN[u][0] = fma2(ha.y, wv.y, aN[u][0]);
                    aN[u][1] = fma2(hb.x, wv.x, aN[u][1]);
                    aN[u][1] = fma2(hb.y, wv.y, aN[u][1]);
                }
            }

#pragma unroll
            for (int u = 0; u < JG; ++u) {
                const int j = j0 + u;
                float bhr = b_hh[j], bhz = b_hh[HD + j], bhn = b_hh[2 * HD + j];
                float xr0 = b_ih[j], xz0 = b_ih[HD + j], xn0 = b_ih[2 * HD + j];
                float wir = w_ih[j], wiz = w_ih[HD + j], win = w_ih[2 * HD + j];
                {   // sample A
                    float hr = red2(aR[u][0]) + bhr, hz = red2(aZ[u][0]) + bhz, hng = red2(aN[u][0]) + bhn;
                    float r = sigm(fmaf(dA, wir, xr0) + hr);
                    float z = sigm(fmaf(dA, wiz, xz0) + hz);
                    float n = tanh_f(fmaf(dA, win, xn0) + r * hng);
                    hn[lane * PITCH + j] = (1.f - z) * n + z * hc[lane * PITCH + j];
                }
                {   // sample B
                    float hr = red2(aR[u][1]) + bhr, hz = red2(aZ[u][1]) + bhz, hng = red2(aN[u][1]) + bhn;
                    float r = sigm(fmaf(dB, wir, xr0) + hr);
                    float z = sigm(fmaf(dB, wiz, xz0) + hz);
                    float n = tanh_f(fmaf(dB, win, xn0) + r * hng);
                    hn[(lane + 32) * PITCH + j] = (1.f - z) * n + z * hc[(lane + 32) * PITCH + j];
                }
            }
        }
        __syncthreads();

        // dec layer 1: [200]->[100]
        for (int ii = 0; ii < 13; ++ii) {
            int i = w + 8 * ii;
            if (i < 100) {
                float b = dec_b1[i];
                const float* wr1 = dec_w1 + (size_t)i * HD;
#pragma unroll
                for (int p = 0; p < 2; ++p) {
                    int s = lane + 32 * p;
                    xbuf[s * 100 + i] = lrelu(dotAB<100>(hn + s * PITCH, wr1) + b);
                }
            }
        }
        __syncthreads();
        // dec layer 2: [100]->[50]
        for (int ii = 0; ii < 7; ++ii) {
            int i = w + 8 * ii;
            if (i < 50) {
                float b = dec_b2[i];
                const float* wr2 = dec_w2 + (size_t)i * 100;
#pragma unroll
                for (int p = 0; p < 2; ++p) {
                    int s = lane + 32 * p;
                    y2b[s * 52 + i] = lrelu(dotAB<50>(xbuf + s * 100, wr2) + b);
                }
            }
        }
        __syncthreads();
        // dec layer 3: [50]->[1]
        if (tid < BT) {
            int s = tid;
            float v = dotAB<25>(y2b + s * 52, dec_w3) + dec_b3[0];
            out[((size_t)(cta * BT + s)) * LD + t] = v;
            din[s] = v;
        }
        __syncthreads();
    }
}

extern "C" void kernel_launch(void* const* d_in, const int* in_sizes, int n_in,
                              void* d_out, int out_size) {
    const float* enc_in = (const float*)d_in[0];
    const float* enc_w1 = (const float*)d_in[1];
    const float* enc_b1 = (const float*)d_in[2];
    const float* enc_w2 = (const float*)d_in[3];
    const float* enc_b2 = (const float*)d_in[4];
    const float* enc_wl = (const float*)d_in[5];
    const float* enc_bl = (const float*)d_in[6];
    const float* w_ih   = (const float*)d_in[7];
    const float* w_hh   = (const float*)d_in[8];
    const float* b_ih   = (const float*)d_in[9];
    const float* b_hh   = (const float*)d_in[10];
    const float* dec_w1 = (const float*)d_in[11];
    const float* dec_b1 = (const float*)d_in[12];
    const float* dec_w2 = (const float*)d_in[13];
    const float* dec_b2 = (const float*)d_in[14];
    const float* dec_w3 = (const float*)d_in[15];
    const float* dec_b3 = (const float*)d_in[16];
    float* out = (float*)d_out;

    cudaFuncSetAttribute(seq2seq_gru_kernel,
                         cudaFuncAttributeMaxDynamicSharedMemorySize, SMEM_BYTES);
    seq2seq_gru_kernel<<<NS / BT, THREADS, SMEM_BYTES>>>(
        enc_in, enc_w1, enc_b1, enc_w2, enc_b2, enc_wl, enc_bl,
        w_ih, w_hh, b_ih, b_hh,
        dec_w1, dec_b1, dec_w2, dec_b2, dec_w3, dec_b3, out);
}